// round 11
// baseline (speedup 1.0000x reference)
#include <cuda_runtime.h>
#include <cuda_bf16.h>

#define IMG_W 512
#define IMG_H 512
#define SUBROWS 32          // rows per warp strip
#define NTHREADS 128        // 4 warps: (colhalf = w&1, subband = w>>1)

// Zero row for out-of-image / past-strip rows: static storage -> zero
// initialized, never written; L2-resident. zbase = g_zrow+4 so
// [col-1, col+8] stays in-bounds for col in [0,504].
__device__ __align__(16) float g_zrow[520];

// 3x3 local variance, stride 1, zero pad 1, divisor 9.
// Warp-autonomous, branch-free row loads (pointer select to zero row) with
// one-row register prefetch; unroll 4 lets ptxas batch several iterations'
// independent LDG.128s ahead of their consumers. Each lane owns 8 contiguous
// columns (2x LDG.128/row). Rolling state: vp (prev row), p (2-row sum),
// q (2-row sq-sum). Vertical 3-sum then horizontal 3-tap via shuffles;
// warp-boundary column via scalar rolling state in lanes 0/31.
__global__ __launch_bounds__(NTHREADS, 8)
void ChannelwiseVariance_85091892068508_kernel(const float* __restrict__ x,
                                               float* __restrict__ out)
{
    const int tid  = threadIdx.x;
    const int lane = tid & 31;
    const int w    = tid >> 5;
    const int colhalf = w & 1;
    const int sub     = w >> 1;
    const int col  = colhalf * 256 + lane * 8;     // first of 8 owned columns
    const int y0   = blockIdx.x * (2 * SUBROWS) + sub * SUBROWS;
    const int rlast = y0 + SUBROWS;                // last input row needed
    const size_t plane = (size_t)blockIdx.y * (size_t)(IMG_H * IMG_W);

    const float* const zbase = g_zrow + 4;
    const bool lane_l = (lane == 0)  && (col != 0);
    const bool lane_r = (lane == 31) && (col + 8 != IMG_W);
    const float inv9 = 1.0f / 9.0f;

    float vp[8], p[8], q[8];
    #pragma unroll
    for (int j = 0; j < 8; ++j) { vp[j] = 0.f; p[j] = 0.f; q[j] = 0.f; }
    float lxp = 0.f, lp = 0.f, lq = 0.f;           // boundary rolling state
    float rxp = 0.f, rp = 0.f, rq = 0.f;           // (lanes 0 / 31)

    // Prologue: prefetch row y0-1 (zero row when y0 == 0).
    const float* nrp = (y0 - 1 >= 0) ? (x + plane + (size_t)(y0 - 1) * IMG_W)
                                     : zbase;
    float4 na = *reinterpret_cast<const float4*>(nrp + col);
    float4 nb = *reinterpret_cast<const float4*>(nrp + col + 4);
    float nl = lane_l ? nrp[col - 1] : 0.0f;
    float nr = lane_r ? nrp[col + 8] : 0.0f;

    #pragma unroll 4
    for (int it = 0; it < SUBROWS + 2; ++it) {
        const int r = y0 - 1 + it;

        // Consume prefetched row r.
        const float4 va = na, vb = nb;
        const float lxn = nl, rxn = nr;

        // Prefetch row r+1 (branch-free: zero row when past the image OR
        // past the last row this strip consumes -> no wasted DRAM reads).
        const int rn = r + 1;                       // >= 0 always
        const bool fetch = (rn < IMG_H) && (rn <= rlast);
        const float* prp = fetch ? (x + plane + (size_t)rn * IMG_W) : zbase;
        na = *reinterpret_cast<const float4*>(prp + col);
        nb = *reinterpret_cast<const float4*>(prp + col + 4);
        nl = lane_l ? prp[col - 1] : 0.0f;
        nr = lane_r ? prp[col + 8] : 0.0f;

        float vc[8];
        vc[0] = va.x; vc[1] = va.y; vc[2] = va.z; vc[3] = va.w;
        vc[4] = vb.x; vc[5] = vb.y; vc[6] = vb.z; vc[7] = vb.w;

        // Vertical 3-sums for output row r-1, then roll state forward.
        float S1[8], S2[8];
        #pragma unroll
        for (int j = 0; j < 8; ++j) {
            const float sq = vc[j] * vc[j];
            S1[j] = p[j] + vc[j];
            S2[j] = q[j] + sq;
            p[j]  = vp[j] + vc[j];
            q[j]  = fmaf(vp[j], vp[j], sq);
            vp[j] = vc[j];
        }
        // Boundary scalars (live in lanes 0 / 31).
        const float lsq = lxn * lxn, rsq = rxn * rxn;
        const float lS1 = lp + lxn, lS2 = lq + lsq;
        const float rS1 = rp + rxn, rS2 = rq + rsq;
        lp = lxp + lxn; lq = fmaf(lxp, lxp, lsq); lxp = lxn;
        rp = rxp + rxn; rq = fmaf(rxp, rxp, rsq); rxp = rxn;

        if (it >= 2) {
            // Horizontal halo of vertical sums via shuffles.
            float sv_l = __shfl_up_sync(0xffffffffu, S1[7], 1);
            float sq_l = __shfl_up_sync(0xffffffffu, S2[7], 1);
            float sv_r = __shfl_down_sync(0xffffffffu, S1[0], 1);
            float sq_r = __shfl_down_sync(0xffffffffu, S2[0], 1);
            if (lane == 0)  { sv_l = lS1; sq_l = lS2; }
            if (lane == 31) { sv_r = rS1; sq_r = rS2; }

            float o[8];
            {
                const float t1 = sv_l + S1[0] + S1[1];
                const float t2 = sq_l + S2[0] + S2[1];
                const float m = t1 * inv9; o[0] = fmaf(-m, m, t2 * inv9);
            }
            #pragma unroll
            for (int j = 1; j < 7; ++j) {
                const float t1 = S1[j - 1] + S1[j] + S1[j + 1];
                const float t2 = S2[j - 1] + S2[j] + S2[j + 1];
                const float m = t1 * inv9; o[j] = fmaf(-m, m, t2 * inv9);
            }
            {
                const float t1 = S1[6] + S1[7] + sv_r;
                const float t2 = S2[6] + S2[7] + sq_r;
                const float m = t1 * inv9; o[7] = fmaf(-m, m, t2 * inv9);
            }

            const int y = r - 1;
            float* op = out + plane + (size_t)y * IMG_W + col;
            __stcs(reinterpret_cast<float4*>(op),
                   make_float4(o[0], o[1], o[2], o[3]));
            __stcs(reinterpret_cast<float4*>(op + 4),
                   make_float4(o[4], o[5], o[6], o[7]));
        }
    }
}

extern "C" void kernel_launch(void* const* d_in, const int* in_sizes, int n_in,
                              void* d_out, int out_size)
{
    const float* x = (const float*)d_in[0];
    float* out = (float*)d_out;

    const int planes = in_sizes[0] / (IMG_H * IMG_W);   // 8*32 = 256
    dim3 grid(IMG_H / (2 * SUBROWS), planes);           // (8, 256) = 2048 blocks
    dim3 block(NTHREADS);
    ChannelwiseVariance_85091892068508_kernel<<<grid, block>>>(x, out);
}

// round 12
// speedup vs baseline: 1.0195x; 1.0195x over previous
#include <cuda_runtime.h>
#include <cuda_bf16.h>

#define IMG_W 512
#define IMG_H 512
#define SUBROWS 32          // rows per warp strip
#define NTHREADS 128        // 4 warps: (colhalf = w&1, subband = w>>1)

// Zero row for out-of-image / past-strip rows: static storage -> zero
// initialized, never written; L2-resident. zbase = g_zrow+4 so
// [col-1, col+8] stays in-bounds for col in [0,504].
__device__ __align__(16) float g_zrow[520];

// 3x3 local variance, stride 1, zero pad 1, divisor 9.
// Warp-autonomous, branch-free row loads (pointer select to zero row) with
// one-row register prefetch. Each lane owns 8 contiguous columns
// (2x LDG.128/row). Rolling state: vp (prev row), p (2-row sum),
// q (2-row sq-sum). Vertical 3-sum then horizontal 3-tap via shuffles;
// warp-boundary column via scalar rolling state in lanes 0/31.
__global__ __launch_bounds__(NTHREADS, 8)
void ChannelwiseVariance_85091892068508_kernel(const float* __restrict__ x,
                                               float* __restrict__ out)
{
    const int tid  = threadIdx.x;
    const int lane = tid & 31;
    const int w    = tid >> 5;
    const int colhalf = w & 1;
    const int sub     = w >> 1;
    const int col  = colhalf * 256 + lane * 8;     // first of 8 owned columns
    const int y0   = blockIdx.x * (2 * SUBROWS) + sub * SUBROWS;
    const int rlast = y0 + SUBROWS;                // last input row needed
    const size_t plane = (size_t)blockIdx.y * (size_t)(IMG_H * IMG_W);

    const float* const zbase = g_zrow + 4;
    const bool lane_l = (lane == 0)  && (col != 0);
    const bool lane_r = (lane == 31) && (col + 8 != IMG_W);
    const float inv9 = 1.0f / 9.0f;

    float vp[8], p[8], q[8];
    #pragma unroll
    for (int j = 0; j < 8; ++j) { vp[j] = 0.f; p[j] = 0.f; q[j] = 0.f; }
    float lxp = 0.f, lp = 0.f, lq = 0.f;           // boundary rolling state
    float rxp = 0.f, rp = 0.f, rq = 0.f;           // (lanes 0 / 31)

    // Prologue: prefetch row y0-1 (zero row when y0 == 0).
    const float* nrp = (y0 - 1 >= 0) ? (x + plane + (size_t)(y0 - 1) * IMG_W)
                                     : zbase;
    float4 na = *reinterpret_cast<const float4*>(nrp + col);
    float4 nb = *reinterpret_cast<const float4*>(nrp + col + 4);
    float nl = lane_l ? nrp[col - 1] : 0.0f;
    float nr = lane_r ? nrp[col + 8] : 0.0f;

    #pragma unroll 2
    for (int it = 0; it < SUBROWS + 2; ++it) {
        const int r = y0 - 1 + it;

        // Consume prefetched row r.
        const float4 va = na, vb = nb;
        const float lxn = nl, rxn = nr;

        // Prefetch row r+1 (branch-free: zero row when past the image OR
        // past the last row this strip consumes -> no wasted DRAM reads).
        const int rn = r + 1;                       // >= 0 always
        const bool fetch = (rn < IMG_H) && (rn <= rlast);
        const float* prp = fetch ? (x + plane + (size_t)rn * IMG_W) : zbase;
        na = *reinterpret_cast<const float4*>(prp + col);
        nb = *reinterpret_cast<const float4*>(prp + col + 4);
        nl = lane_l ? prp[col - 1] : 0.0f;
        nr = lane_r ? prp[col + 8] : 0.0f;

        float vc[8];
        vc[0] = va.x; vc[1] = va.y; vc[2] = va.z; vc[3] = va.w;
        vc[4] = vb.x; vc[5] = vb.y; vc[6] = vb.z; vc[7] = vb.w;

        // Vertical 3-sums for output row r-1, then roll state forward.
        float S1[8], S2[8];
        #pragma unroll
        for (int j = 0; j < 8; ++j) {
            const float sq = vc[j] * vc[j];
            S1[j] = p[j] + vc[j];
            S2[j] = q[j] + sq;
            p[j]  = vp[j] + vc[j];
            q[j]  = fmaf(vp[j], vp[j], sq);
            vp[j] = vc[j];
        }
        // Boundary scalars (live in lanes 0 / 31).
        const float lsq = lxn * lxn, rsq = rxn * rxn;
        const float lS1 = lp + lxn, lS2 = lq + lsq;
        const float rS1 = rp + rxn, rS2 = rq + rsq;
        lp = lxp + lxn; lq = fmaf(lxp, lxp, lsq); lxp = lxn;
        rp = rxp + rxn; rq = fmaf(rxp, rxp, rsq); rxp = rxn;

        if (it >= 2) {
            // Horizontal halo of vertical sums via shuffles.
            float sv_l = __shfl_up_sync(0xffffffffu, S1[7], 1);
            float sq_l = __shfl_up_sync(0xffffffffu, S2[7], 1);
            float sv_r = __shfl_down_sync(0xffffffffu, S1[0], 1);
            float sq_r = __shfl_down_sync(0xffffffffu, S2[0], 1);
            if (lane == 0)  { sv_l = lS1; sq_l = lS2; }
            if (lane == 31) { sv_r = rS1; sq_r = rS2; }

            float o[8];
            {
                const float t1 = sv_l + S1[0] + S1[1];
                const float t2 = sq_l + S2[0] + S2[1];
                const float m = t1 * inv9; o[0] = fmaf(-m, m, t2 * inv9);
            }
            #pragma unroll
            for (int j = 1; j < 7; ++j) {
                const float t1 = S1[j - 1] + S1[j] + S1[j + 1];
                const float t2 = S2[j - 1] + S2[j] + S2[j + 1];
                const float m = t1 * inv9; o[j] = fmaf(-m, m, t2 * inv9);
            }
            {
                const float t1 = S1[6] + S1[7] + sv_r;
                const float t2 = S2[6] + S2[7] + sq_r;
                const float m = t1 * inv9; o[7] = fmaf(-m, m, t2 * inv9);
            }

            const int y = r - 1;
            float* op = out + plane + (size_t)y * IMG_W + col;
            __stcs(reinterpret_cast<float4*>(op),
                   make_float4(o[0], o[1], o[2], o[3]));
            __stcs(reinterpret_cast<float4*>(op + 4),
                   make_float4(o[4], o[5], o[6], o[7]));
        }
    }
}

extern "C" void kernel_launch(void* const* d_in, const int* in_sizes, int n_in,
                              void* d_out, int out_size)
{
    const float* x = (const float*)d_in[0];
    float* out = (float*)d_out;

    const int planes = in_sizes[0] / (IMG_H * IMG_W);   // 8*32 = 256
    dim3 grid(IMG_H / (2 * SUBROWS), planes);           // (8, 256) = 2048 blocks
    dim3 block(NTHREADS);
    ChannelwiseVariance_85091892068508_kernel<<<grid, block>>>(x, out);
}